// round 15
// baseline (speedup 1.0000x reference)
#include <cuda_runtime.h>
#include <cstdint>

#define N_NODES 100000
#define N_EDGES 1600000
#define N_GRAPHS 512
#define D 64
#define BN_EPS 1e-5f
#define NREP 16   // stats replicas to de-serialize atomics

// ------------------------- device scratch (no allocs allowed) ---------------
__device__ __align__(16) float g_sums[(size_t)N_NODES * D];   // scatter accumulator
__device__ __align__(16) float g_cnt[N_NODES];
__device__ __align__(16) float g_bufA[(size_t)N_NODES * D];
__device__ __align__(16) float g_bufB[(size_t)N_NODES * D];
__device__ float g_stats[3 * NREP * 128];       // [layer][replica][sum64|sumsq64]
__device__ int g_is64;                          // 1 if indices are int64

// ------------------------- helpers ------------------------------------------
__device__ __forceinline__ void ffma2(unsigned long long& d, unsigned long long a,
                                      unsigned long long b) {
    asm("fma.rn.f32x2 %0, %1, %2, %0;" : "+l"(d) : "l"(a), "l"(b));
}
__device__ __forceinline__ unsigned long long pack2(float v) {
    unsigned long long r;
    asm("mov.b64 %0, {%1, %1};" : "=l"(r) : "f"(v));
    return r;
}
__device__ __forceinline__ void unpack2(unsigned long long p, float& lo, float& hi) {
    asm("mov.b64 {%0, %1}, %2;" : "=f"(lo), "=f"(hi) : "l"(p));
}
// Load index i from an array that may be int32 or int64 (flag-selected).
__device__ __forceinline__ int load_idx(const void* p, int i, int is64, int lim) {
    int v;
    if (is64) v = (int)__ldg(reinterpret_cast<const long long*>(p) + i);
    else      v = __ldg(reinterpret_cast<const int*>(p) + i);
    return min(max(v, 0), lim - 1);  // defensive clamp: never fault
}

// --------------- zero scratch (2 launches so k_layer1 = launch #4) -----------
__global__ void k_zero1() {   // g_sums (1.6M float4) + g_cnt (25K float4)
    int i = blockIdx.x * blockDim.x + threadIdx.x;
    reinterpret_cast<float4*>(g_sums)[i] = make_float4(0.f, 0.f, 0.f, 0.f);
    if (i < N_NODES / 4)
        reinterpret_cast<float4*>(g_cnt)[i] = make_float4(0.f, 0.f, 0.f, 0.f);
}
__global__ void k_zero2(const int* __restrict__ ei32) {  // stats + dtype detect
    int t = threadIdx.x;
    for (int i = t; i < 3 * NREP * 128; i += 256) g_stats[i] = 0.f;
    if (t == 0) {
        // int64 data (values < 2^31) -> odd 32-bit words are zero high-words.
        int nz = 0;
        for (int k = 1; k < 64; k += 2) nz |= ei32[k];
        g_is64 = (nz == 0) ? 1 : 0;
    }
}

// ------------------------- edge scatter (segment_sum + counts) ---------------
// 8 threads per edge, 32B (v8.b32) streaming loads with evict_first.
__global__ void k_scatter(const void* __restrict__ src,
                          const float* __restrict__ ea) {
    int idx = blockIdx.x * blockDim.x + threadIdx.x;  // E*8 threads
    int e = idx >> 3;
    if (e >= N_EDGES) return;
    int q = idx & 7;
    int is64 = g_is64;
    int s = load_idx(src, e, is64, N_NODES);
    unsigned u0, u1, u2, u3, u4, u5, u6, u7;
    asm("ld.global.nc.L2::evict_first.v8.b32 {%0,%1,%2,%3,%4,%5,%6,%7}, [%8];"
        : "=r"(u0), "=r"(u1), "=r"(u2), "=r"(u3),
          "=r"(u4), "=r"(u5), "=r"(u6), "=r"(u7)
        : "l"(ea + (size_t)e * D + q * 8));
    float* dst = g_sums + (size_t)s * D + q * 8;
    asm volatile("red.global.add.v4.f32 [%0], {%1,%2,%3,%4};"
                 :: "l"(dst),
                    "f"(__uint_as_float(u0)), "f"(__uint_as_float(u1)),
                    "f"(__uint_as_float(u2)), "f"(__uint_as_float(u3)) : "memory");
    asm volatile("red.global.add.v4.f32 [%0], {%1,%2,%3,%4};"
                 :: "l"(dst + 4),
                    "f"(__uint_as_float(u4)), "f"(__uint_as_float(u5)),
                    "f"(__uint_as_float(u6)), "f"(__uint_as_float(u7)) : "memory");
    if (q == 0)
        asm volatile("red.global.add.f32 [%0], %1;"
                     :: "l"(g_cnt + s), "f"(1.0f) : "memory");
}

// ------------- GEMM inner chunk: 8 rows x 8 cols per thread, 32 k-steps ------
// rows: rg + 16j (j=0..7), cols: cg*4..+3 and cg*4+32..+35.
__device__ __forceinline__ void mma_chunk(
    const float (*in_s)[36], const float* W_s, int rg, int cg,
    unsigned long long acc[8][4]) {
#pragma unroll
    for (int kk = 0; kk < 32; kk++) {
        const ulonglong2* wrow = reinterpret_cast<const ulonglong2*>(W_s + kk * 64);
        ulonglong2 wa = wrow[cg], wb = wrow[cg + 8];
#pragma unroll
        for (int j = 0; j < 8; j++) {
            unsigned long long ra = pack2(in_s[rg + 16 * j][kk]);
            ffma2(acc[j][0], ra, wa.x); ffma2(acc[j][1], ra, wa.y);
            ffma2(acc[j][2], ra, wb.x); ffma2(acc[j][3], ra, wb.y);
        }
    }
}

// =============== epilogue: bias + relu + store + block stats =================
__device__ __forceinline__ void epilogue(
    unsigned long long acc[8][4], const float* b_s, float (*red_s)[2][64],
    int t, int rg, int cg, int rowBase, int rep,
    float* __restrict__ out, float* __restrict__ st) {
    int c0 = cg * 4;
    float s[8] = {0, 0, 0, 0, 0, 0, 0, 0};
    float s2[8] = {0, 0, 0, 0, 0, 0, 0, 0};
#pragma unroll
    for (int j = 0; j < 8; j++) {
        float r[8];
        unpack2(acc[j][0], r[0], r[1]); unpack2(acc[j][1], r[2], r[3]);
        unpack2(acc[j][2], r[4], r[5]); unpack2(acc[j][3], r[6], r[7]);
#pragma unroll
        for (int i = 0; i < 4; i++) {
            r[i] = fmaxf(r[i] + b_s[c0 + i], 0.f);
            r[4 + i] = fmaxf(r[4 + i] + b_s[c0 + 32 + i], 0.f);
        }
        int grow = rowBase + rg + 16 * j;
        if (grow < N_NODES) {
            float4* o = reinterpret_cast<float4*>(out + (size_t)grow * D);
            o[cg] = make_float4(r[0], r[1], r[2], r[3]);
            o[cg + 8] = make_float4(r[4], r[5], r[6], r[7]);
#pragma unroll
            for (int i = 0; i < 8; i++) { s[i] += r[i]; s2[i] += r[i] * r[i]; }
        }
    }
    // reduce across the 4 rg-subgroups within the warp (lane bits 3,4)
#pragma unroll
    for (int m = 8; m <= 16; m <<= 1) {
#pragma unroll
        for (int i = 0; i < 8; i++) {
            s[i] += __shfl_xor_sync(0xffffffffu, s[i], m);
            s2[i] += __shfl_xor_sync(0xffffffffu, s2[i], m);
        }
    }
    int warp = t >> 5, lane = t & 31;
    if (lane < 8) {
#pragma unroll
        for (int i = 0; i < 4; i++) {
            red_s[warp][0][lane * 4 + i] = s[i];
            red_s[warp][0][lane * 4 + 32 + i] = s[4 + i];
            red_s[warp][1][lane * 4 + i] = s2[i];
            red_s[warp][1][lane * 4 + 32 + i] = s2[4 + i];
        }
    }
    __syncthreads();
    {
        int which = t >> 6, col = t & 63;  // 128 threads -> which in {0,1}
        float a = red_s[0][which][col] + red_s[1][which][col] +
                  red_s[2][which][col] + red_s[3][which][col];
        atomicAdd(st + rep * 128 + which * 64 + col, a);
    }
}

// ------------------------- layer 1: comb[192] @ W1 + b1, relu + stats --------
// in_s staged in 32-k chunks to keep smem ~29KB (7 blocks/SM).
__global__ __launch_bounds__(128) void k_layer1(
        const float* __restrict__ x,
        const float* __restrict__ ga,
        const void* __restrict__ batch,
        const float* __restrict__ W1,
        const float* __restrict__ b1,
        float* __restrict__ out,
        float* __restrict__ st) {
    __shared__ __align__(16) float in_s[128][36];
    __shared__ __align__(16) float W_s[32 * 64];
    __shared__ float red_s[4][2][64];
    __shared__ float b_s[64];
    __shared__ int batch_s[128];

    int t = threadIdx.x;
    int rowBase = blockIdx.x * 128;
    if (t < 64) b_s[t] = b1[t];
    {
        int gr = rowBase + t;
        batch_s[t] = (gr < N_NODES) ? load_idx(batch, gr, g_is64, N_GRAPHS) : 0;
    }
    int rg = t >> 3, cg = t & 7;
    unsigned long long acc[8][4] = {};

    for (int sdx = 0; sdx < 6; sdx++) {
        int c = sdx >> 1, half = sdx & 1;
        __syncthreads();
        // stage in_s: 128 rows x 32 cols (source c, column half)
        for (int i = t; i < 1024; i += 128) {
            int rr = i >> 3, c4 = i & 7;
            int gr = rowBase + rr;
            float4 v = make_float4(0.f, 0.f, 0.f, 0.f);
            if (gr < N_NODES) {
                int fidx = gr * 16 + half * 8 + c4;
                if (c == 0) {
                    v = reinterpret_cast<const float4*>(x)[fidx];
                } else if (c == 1) {
                    v = reinterpret_cast<const float4*>(g_sums)[fidx];
                    float inv = 1.0f / fmaxf(g_cnt[gr], 1.0f);
                    v.x *= inv; v.y *= inv; v.z *= inv; v.w *= inv;
                } else {
                    v = reinterpret_cast<const float4*>(ga)[batch_s[rr] * 16 +
                                                            half * 8 + c4];
                }
            }
            *reinterpret_cast<float4*>(&in_s[rr][c4 * 4]) = v;
        }
        // stage W chunk: k rows sdx*32 .. sdx*32+31
        for (int i = t; i < 512; i += 128)
            reinterpret_cast<float4*>(W_s)[i] =
                reinterpret_cast<const float4*>(W1 + sdx * 2048)[i];
        __syncthreads();
        mma_chunk(in_s, W_s, rg, cg, acc);
    }
    __syncthreads();
    epilogue(acc, b_s, red_s, t, rg, cg, rowBase, blockIdx.x & (NREP - 1), out, st);
}

// --------- layers 2/3: BN(prev stats) folded into W on the fly, relu + stats -
__global__ __launch_bounds__(128) void k_layer64(
        const float* __restrict__ in,
        const float* __restrict__ W,      // raw weights [64][64]
        const float* __restrict__ b,      // raw bias
        const float* __restrict__ st,     // prev-layer stats (NREP replicas)
        const float* __restrict__ g,      // prev-layer BN gamma
        const float* __restrict__ bt,     // prev-layer BN beta
        float* __restrict__ out,
        float* __restrict__ st_out) {
    __shared__ __align__(16) float in_s[128][36];
    __shared__ __align__(16) float W_s[32 * 64];
    __shared__ float red_s[4][2][64];
    __shared__ float a_s[64], c_s[64], b_s[64];
    __shared__ float bred[2][64];

    int t = threadIdx.x;
    int rowBase = blockIdx.x * 128;

    // stage 0: BN fold coefficients from prev-layer stats (sum replicas)
    if (t < 64) {
        float sum = 0.f, sumsq = 0.f;
#pragma unroll
        for (int rep = 0; rep < NREP; rep++) {
            sum += st[rep * 128 + t];
            sumsq += st[rep * 128 + 64 + t];
        }
        const float invN = 1.0f / (float)N_NODES;
        float mean = sum * invN;
        float var = sumsq * invN - mean * mean;
        float a = g[t] * rsqrtf(var + BN_EPS);
        a_s[t] = a;
        c_s[t] = bt[t] - mean * a;
    }
    __syncthreads();

    // folded-bias partials (reads raw W from global; c_s ready)
    {
        int q = t >> 6, col = t & 63;
        float acc = 0.f;
#pragma unroll
        for (int kk = 0; kk < 32; kk++) {
            int k = q * 32 + kk;
            acc += c_s[k] * __ldg(W + k * 64 + col);
        }
        bred[q][col] = acc;
    }
    __syncthreads();
    if (t < 64) b_s[t] = b[t] + bred[0][t] + bred[1][t];

    int rg = t >> 3, cg = t & 7;
    unsigned long long acc[8][4] = {};

    for (int h = 0; h < 2; h++) {
        __syncthreads();
        // stage in_s: 128 rows x 32 cols (column half h)
        for (int i = t; i < 1024; i += 128) {
            int rr = i >> 3, c4 = i & 7;
            int gr = rowBase + rr;
            float4 v = (gr < N_NODES)
                           ? reinterpret_cast<const float4*>(in)[gr * 16 + h * 8 + c4]
                           : make_float4(0.f, 0.f, 0.f, 0.f);
            *reinterpret_cast<float4*>(&in_s[rr][c4 * 4]) = v;
        }
        // stage W chunk scaled by a_s[k]
        for (int i = t; i < 512; i += 128) {
            int k = h * 32 + (i >> 4);
            float4 w = reinterpret_cast<const float4*>(W + h * 2048)[i];
            float a = a_s[k];
            w.x *= a; w.y *= a; w.z *= a; w.w *= a;
            reinterpret_cast<float4*>(W_s)[i] = w;
        }
        __syncthreads();
        mma_chunk(in_s, W_s, rg, cg, acc);
    }
    __syncthreads();
    epilogue(acc, b_s, red_s, t, rg, cg, rowBase, blockIdx.x & (NREP - 1),
             out, st_out);
}

// -------------- final: BN(stats3) applied as per-column affine ---------------
__global__ __launch_bounds__(256) void k_final(
        const float* __restrict__ h, const float* __restrict__ st,
        const float* __restrict__ g, const float* __restrict__ bt,
        float* __restrict__ out) {
    __shared__ float a_s[64], c_s[64];
    int t = threadIdx.x;
    if (t < 64) {
        float sum = 0.f, sumsq = 0.f;
#pragma unroll
        for (int rep = 0; rep < NREP; rep++) {
            sum += st[rep * 128 + t];
            sumsq += st[rep * 128 + 64 + t];
        }
        const float invN = 1.0f / (float)N_NODES;
        float mean = sum * invN;
        float var = sumsq * invN - mean * mean;
        float a = g[t] * rsqrtf(var + BN_EPS);
        a_s[t] = a;
        c_s[t] = bt[t] - mean * a;
    }
    __syncthreads();
    int i = blockIdx.x * blockDim.x + t;  // float4 index
    if (i >= N_NODES * 16) return;
    int c4 = (i & 15) * 4;
    float4 v = reinterpret_cast<const float4*>(h)[i];
    v.x = v.x * a_s[c4 + 0] + c_s[c4 + 0];
    v.y = v.y * a_s[c4 + 1] + c_s[c4 + 1];
    v.z = v.z * a_s[c4 + 2] + c_s[c4 + 2];
    v.w = v.w * a_s[c4 + 3] + c_s[c4 + 3];
    reinterpret_cast<float4*>(out)[i] = v;
}

// ------------------------- launch -------------------------------------------
extern "C" void kernel_launch(void* const* d_in, const int* in_sizes, int n_in,
                              void* d_out, int out_size) {
    const float* x = (const float*)d_in[0];
    const void* ei = d_in[1];          // int32 or int64 — detected on device
    const float* ea = (const float*)d_in[2];
    const float* ga = (const float*)d_in[3];
    const void* batch = d_in[4];       // int32 or int64 — detected on device
    const float* W1 = (const float*)d_in[5];
    const float* b1 = (const float*)d_in[6];
    const float* W2 = (const float*)d_in[7];
    const float* b2 = (const float*)d_in[8];
    const float* W3 = (const float*)d_in[9];
    const float* b3 = (const float*)d_in[10];
    const float* g1 = (const float*)d_in[11];
    const float* bt1 = (const float*)d_in[12];
    const float* g2 = (const float*)d_in[13];
    const float* bt2 = (const float*)d_in[14];
    const float* g3 = (const float*)d_in[15];
    const float* bt3 = (const float*)d_in[16];
    float* out = (float*)d_out;

    float *pA, *pB, *pStats;
    cudaGetSymbolAddress((void**)&pA, g_bufA);
    cudaGetSymbolAddress((void**)&pB, g_bufB);
    cudaGetSymbolAddress((void**)&pStats, g_stats);

    const int rowBlocks = (N_NODES + 127) / 128;  // 782
    const int L = NREP * 128;                      // stats stride per layer

    // launch order: k_layer1 is launch #4 (the one ncu -s 5 -c 1 captures)
    k_zero1<<<6250, 256>>>();
    k_zero2<<<1, 256>>>((const int*)ei);
    k_scatter<<<(N_EDGES * 8) / 256, 256>>>(ei, ea);
    k_layer1<<<rowBlocks, 128>>>(x, ga, batch, W1, b1, pA, pStats);
    k_layer64<<<rowBlocks, 128>>>(pA, W2, b2, pStats, g1, bt1, pB, pStats + L);
    k_layer64<<<rowBlocks, 128>>>(pB, W3, b3, pStats + L, g2, bt2, pA, pStats + 2 * L);
    k_final<<<(N_NODES * 16 + 255) / 256, 256>>>(pA, pStats + 2 * L, g3, bt3, out);
}

// round 16
// speedup vs baseline: 1.0983x; 1.0983x over previous
#include <cuda_runtime.h>
#include <cstdint>

#define N_NODES 100000
#define N_EDGES 1600000
#define N_GRAPHS 512
#define D 64
#define BN_EPS 1e-5f
#define NREP 16   // stats replicas to de-serialize atomics

// ------------------------- device scratch (no allocs allowed) ---------------
__device__ __align__(16) float g_sums[(size_t)N_NODES * D];   // scatter accumulator
__device__ __align__(16) float g_cnt[N_NODES];
__device__ __align__(16) float g_bufA[(size_t)N_NODES * D];
__device__ __align__(16) float g_bufB[(size_t)N_NODES * D];
__device__ float g_stats[3 * NREP * 128];       // [layer][replica][sum64|sumsq64]
__device__ int g_is64;                          // 1 if indices are int64

// ------------------------- helpers ------------------------------------------
__device__ __forceinline__ void ffma2(unsigned long long& d, unsigned long long a,
                                      unsigned long long b) {
    asm("fma.rn.f32x2 %0, %1, %2, %0;" : "+l"(d) : "l"(a), "l"(b));
}
__device__ __forceinline__ unsigned long long pack2(float v) {
    unsigned long long r;
    asm("mov.b64 %0, {%1, %1};" : "=l"(r) : "f"(v));
    return r;
}
__device__ __forceinline__ void unpack2(unsigned long long p, float& lo, float& hi) {
    asm("mov.b64 {%0, %1}, %2;" : "=f"(lo), "=f"(hi) : "l"(p));
}
// Load index i from an array that may be int32 or int64 (flag-selected).
__device__ __forceinline__ int load_idx(const void* p, int i, int is64, int lim) {
    int v;
    if (is64) v = (int)__ldg(reinterpret_cast<const long long*>(p) + i);
    else      v = __ldg(reinterpret_cast<const int*>(p) + i);
    return min(max(v, 0), lim - 1);  // defensive clamp: never fault
}

// --------------- zero scratch (2 launches so k_layer1 = launch #4) -----------
__global__ void k_zero1() {   // g_sums (1.6M float4) + g_cnt (25K float4)
    int i = blockIdx.x * blockDim.x + threadIdx.x;
    reinterpret_cast<float4*>(g_sums)[i] = make_float4(0.f, 0.f, 0.f, 0.f);
    if (i < N_NODES / 4)
        reinterpret_cast<float4*>(g_cnt)[i] = make_float4(0.f, 0.f, 0.f, 0.f);
}
__global__ void k_zero2(const int* __restrict__ ei32) {  // stats + dtype detect
    int t = threadIdx.x;
    for (int i = t; i < 3 * NREP * 128; i += 256) g_stats[i] = 0.f;
    if (t == 0) {
        // int64 data (values < 2^31) -> odd 32-bit words are zero high-words.
        int nz = 0;
        for (int k = 1; k < 64; k += 2) nz |= ei32[k];
        g_is64 = (nz == 0) ? 1 : 0;
    }
}

// ------------------------- edge scatter (segment_sum + counts) ---------------
// 16 threads/edge, plain v4 loads (fastest measured form: 103.8us in R10).
__global__ void k_scatter(const void* __restrict__ src,
                          const float* __restrict__ ea) {
    int idx = blockIdx.x * blockDim.x + threadIdx.x;  // E*16 threads
    int e = idx >> 4;
    if (e >= N_EDGES) return;
    int q = idx & 15;
    int is64 = g_is64;
    int s = load_idx(src, e, is64, N_NODES);
    float4 v;
    asm("ld.global.nc.v4.f32 {%0,%1,%2,%3}, [%4];"
        : "=f"(v.x), "=f"(v.y), "=f"(v.z), "=f"(v.w)
        : "l"(ea + (size_t)e * D + q * 4));
    float* dst = g_sums + (size_t)s * D + q * 4;
    asm volatile("red.global.add.v4.f32 [%0], {%1,%2,%3,%4};"
                 :: "l"(dst), "f"(v.x), "f"(v.y), "f"(v.z), "f"(v.w) : "memory");
    if (q == 0)
        asm volatile("red.global.add.f32 [%0], %1;"
                     :: "l"(g_cnt + s), "f"(1.0f) : "memory");
}

// ------------- GEMM inner chunk: 4 rows x 8 cols per thread, 32 k-steps ------
// 256 threads: rg = t>>3 (0..31), rows rg+32j (j=0..3); cols cg*4 and cg*4+32.
__device__ __forceinline__ void mma_chunk(
    const float (*in_s)[36], const float* W_s, int rg, int cg,
    unsigned long long acc[4][4]) {
#pragma unroll
    for (int kk = 0; kk < 32; kk++) {
        const ulonglong2* wrow = reinterpret_cast<const ulonglong2*>(W_s + kk * 64);
        ulonglong2 wa = wrow[cg], wb = wrow[cg + 8];
#pragma unroll
        for (int j = 0; j < 4; j++) {
            unsigned long long ra = pack2(in_s[rg + 32 * j][kk]);
            ffma2(acc[j][0], ra, wa.x); ffma2(acc[j][1], ra, wa.y);
            ffma2(acc[j][2], ra, wb.x); ffma2(acc[j][3], ra, wb.y);
        }
    }
}

// =============== epilogue: bias + relu + store + block stats =================
__device__ __forceinline__ void epilogue(
    unsigned long long acc[4][4], const float* b_s, float (*red_s)[2][64],
    int t, int rg, int cg, int rowBase, int rep,
    float* __restrict__ out, float* __restrict__ st) {
    int c0 = cg * 4;
    float s[8] = {0, 0, 0, 0, 0, 0, 0, 0};
    float s2[8] = {0, 0, 0, 0, 0, 0, 0, 0};
#pragma unroll
    for (int j = 0; j < 4; j++) {
        float r[8];
        unpack2(acc[j][0], r[0], r[1]); unpack2(acc[j][1], r[2], r[3]);
        unpack2(acc[j][2], r[4], r[5]); unpack2(acc[j][3], r[6], r[7]);
#pragma unroll
        for (int i = 0; i < 4; i++) {
            r[i] = fmaxf(r[i] + b_s[c0 + i], 0.f);
            r[4 + i] = fmaxf(r[4 + i] + b_s[c0 + 32 + i], 0.f);
        }
        int grow = rowBase + rg + 32 * j;
        if (grow < N_NODES) {
            float4* o = reinterpret_cast<float4*>(out + (size_t)grow * D);
            o[cg] = make_float4(r[0], r[1], r[2], r[3]);
            o[cg + 8] = make_float4(r[4], r[5], r[6], r[7]);
#pragma unroll
            for (int i = 0; i < 8; i++) { s[i] += r[i]; s2[i] += r[i] * r[i]; }
        }
    }
    // reduce across the 4 rg-subgroups within the warp (lane bits 3,4)
#pragma unroll
    for (int m = 8; m <= 16; m <<= 1) {
#pragma unroll
        for (int i = 0; i < 8; i++) {
            s[i] += __shfl_xor_sync(0xffffffffu, s[i], m);
            s2[i] += __shfl_xor_sync(0xffffffffu, s2[i], m);
        }
    }
    int warp = t >> 5, lane = t & 31;
    if (lane < 8) {
#pragma unroll
        for (int i = 0; i < 4; i++) {
            red_s[warp][0][lane * 4 + i] = s[i];
            red_s[warp][0][lane * 4 + 32 + i] = s[4 + i];
            red_s[warp][1][lane * 4 + i] = s2[i];
            red_s[warp][1][lane * 4 + 32 + i] = s2[4 + i];
        }
    }
    __syncthreads();
    if (t < 128) {
        int which = t >> 6, col = t & 63;
        float a = 0.f;
#pragma unroll
        for (int w = 0; w < 8; w++) a += red_s[w][which][col];
        atomicAdd(st + rep * 128 + which * 64 + col, a);
    }
}

// ------------------------- layer 1: comb[192] @ W1 + b1, relu + stats --------
__global__ __launch_bounds__(256, 3) void k_layer1(
        const float* __restrict__ x,
        const float* __restrict__ ga,
        const void* __restrict__ batch,
        const float* __restrict__ W1,
        const float* __restrict__ b1,
        float* __restrict__ out,
        float* __restrict__ st) {
    __shared__ __align__(16) float in_s[128][36];
    __shared__ __align__(16) float W_s[32 * 64];
    __shared__ float red_s[8][2][64];
    __shared__ float b_s[64];
    __shared__ int batch_s[128];

    int t = threadIdx.x;
    int rowBase = blockIdx.x * 128;
    if (t < 64) b_s[t] = b1[t];
    if (t < 128) {
        int gr = rowBase + t;
        batch_s[t] = (gr < N_NODES) ? load_idx(batch, gr, g_is64, N_GRAPHS) : 0;
    }
    int rg = t >> 3, cg = t & 7;
    unsigned long long acc[4][4] = {};

    for (int sdx = 0; sdx < 6; sdx++) {
        int c = sdx >> 1, half = sdx & 1;
        __syncthreads();
        // stage in_s: 128 rows x 32 cols (source c, column half)
        for (int i = t; i < 1024; i += 256) {
            int rr = i >> 3, c4 = i & 7;
            int gr = rowBase + rr;
            float4 v = make_float4(0.f, 0.f, 0.f, 0.f);
            if (gr < N_NODES) {
                int fidx = gr * 16 + half * 8 + c4;
                if (c == 0) {
                    v = reinterpret_cast<const float4*>(x)[fidx];
                } else if (c == 1) {
                    v = reinterpret_cast<const float4*>(g_sums)[fidx];
                    float inv = 1.0f / fmaxf(g_cnt[gr], 1.0f);
                    v.x *= inv; v.y *= inv; v.z *= inv; v.w *= inv;
                } else {
                    v = reinterpret_cast<const float4*>(ga)[batch_s[rr] * 16 +
                                                            half * 8 + c4];
                }
            }
            *reinterpret_cast<float4*>(&in_s[rr][c4 * 4]) = v;
        }
        // stage W chunk: k rows sdx*32 .. sdx*32+31
        for (int i = t; i < 512; i += 256)
            reinterpret_cast<float4*>(W_s)[i] =
                reinterpret_cast<const float4*>(W1 + sdx * 2048)[i];
        __syncthreads();
        mma_chunk(in_s, W_s, rg, cg, acc);
    }
    __syncthreads();
    epilogue(acc, b_s, red_s, t, rg, cg, rowBase, blockIdx.x & (NREP - 1), out, st);
}

// --------- layers 2/3: BN(prev stats) folded into W on the fly, relu + stats -
__global__ __launch_bounds__(256, 3) void k_layer64(
        const float* __restrict__ in,
        const float* __restrict__ W,      // raw weights [64][64]
        const float* __restrict__ b,      // raw bias
        const float* __restrict__ st,     // prev-layer stats (NREP replicas)
        const float* __restrict__ g,      // prev-layer BN gamma
        const float* __restrict__ bt,     // prev-layer BN beta
        float* __restrict__ out,
        float* __restrict__ st_out) {
    __shared__ __align__(16) float in_s[128][36];
    __shared__ __align__(16) float W_s[32 * 64];
    __shared__ float red_s[8][2][64];
    __shared__ float a_s[64], c_s[64], b_s[64];
    __shared__ float bred[4][64];

    int t = threadIdx.x;
    int rowBase = blockIdx.x * 128;

    // stage 0: BN fold coefficients from prev-layer stats (sum replicas)
    if (t < 64) {
        float sum = 0.f, sumsq = 0.f;
#pragma unroll
        for (int rep = 0; rep < NREP; rep++) {
            sum += st[rep * 128 + t];
            sumsq += st[rep * 128 + 64 + t];
        }
        const float invN = 1.0f / (float)N_NODES;
        float mean = sum * invN;
        float var = sumsq * invN - mean * mean;
        float a = g[t] * rsqrtf(var + BN_EPS);
        a_s[t] = a;
        c_s[t] = bt[t] - mean * a;
    }
    __syncthreads();

    // folded-bias partials (reads raw W from global; c_s ready)
    {
        int q = t >> 6, col = t & 63;
        float acc = 0.f;
#pragma unroll
        for (int kk = 0; kk < 16; kk++) {
            int k = q * 16 + kk;
            acc += c_s[k] * __ldg(W + k * 64 + col);
        }
        bred[q][col] = acc;
    }
    __syncthreads();
    if (t < 64) b_s[t] = b[t] + bred[0][t] + bred[1][t] + bred[2][t] + bred[3][t];

    int rg = t >> 3, cg = t & 7;
    unsigned long long acc[4][4] = {};

    for (int h = 0; h < 2; h++) {
        __syncthreads();
        // stage in_s: 128 rows x 32 cols (column half h)
        for (int i = t; i < 1024; i += 256) {
            int rr = i >> 3, c4 = i & 7;
            int gr = rowBase + rr;
            float4 v = (gr < N_NODES)
                           ? reinterpret_cast<const float4*>(in)[gr * 16 + h * 8 + c4]
                           : make_float4(0.f, 0.f, 0.f, 0.f);
            *reinterpret_cast<float4*>(&in_s[rr][c4 * 4]) = v;
        }
        // stage W chunk scaled by a_s[k]
        for (int i = t; i < 512; i += 256) {
            int k = h * 32 + (i >> 4);
            float4 w = reinterpret_cast<const float4*>(W + h * 2048)[i];
            float a = a_s[k];
            w.x *= a; w.y *= a; w.z *= a; w.w *= a;
            reinterpret_cast<float4*>(W_s)[i] = w;
        }
        __syncthreads();
        mma_chunk(in_s, W_s, rg, cg, acc);
    }
    __syncthreads();
    epilogue(acc, b_s, red_s, t, rg, cg, rowBase, blockIdx.x & (NREP - 1),
             out, st_out);
}

// -------------- final: BN(stats3) applied as per-column affine ---------------
__global__ __launch_bounds__(256) void k_final(
        const float* __restrict__ h, const float* __restrict__ st,
        const float* __restrict__ g, const float* __restrict__ bt,
        float* __restrict__ out) {
    __shared__ float a_s[64], c_s[64];
    int t = threadIdx.x;
    if (t < 64) {
        float sum = 0.f, sumsq = 0.f;
#pragma unroll
        for (int rep = 0; rep < NREP; rep++) {
            sum += st[rep * 128 + t];
            sumsq += st[rep * 128 + 64 + t];
        }
        const float invN = 1.0f / (float)N_NODES;
        float mean = sum * invN;
        float var = sumsq * invN - mean * mean;
        float a = g[t] * rsqrtf(var + BN_EPS);
        a_s[t] = a;
        c_s[t] = bt[t] - mean * a;
    }
    __syncthreads();
    int i = blockIdx.x * blockDim.x + t;  // float4 index
    if (i >= N_NODES * 16) return;
    int c4 = (i & 15) * 4;
    float4 v = reinterpret_cast<const float4*>(h)[i];
    v.x = v.x * a_s[c4 + 0] + c_s[c4 + 0];
    v.y = v.y * a_s[c4 + 1] + c_s[c4 + 1];
    v.z = v.z * a_s[c4 + 2] + c_s[c4 + 2];
    v.w = v.w * a_s[c4 + 3] + c_s[c4 + 3];
    reinterpret_cast<float4*>(out)[i] = v;
}

// ------------------------- launch -------------------------------------------
extern "C" void kernel_launch(void* const* d_in, const int* in_sizes, int n_in,
                              void* d_out, int out_size) {
    const float* x = (const float*)d_in[0];
    const void* ei = d_in[1];          // int32 or int64 — detected on device
    const float* ea = (const float*)d_in[2];
    const float* ga = (const float*)d_in[3];
    const void* batch = d_in[4];       // int32 or int64 — detected on device
    const float* W1 = (const float*)d_in[5];
    const float* b1 = (const float*)d_in[6];
    const float* W2 = (const float*)d_in[7];
    const float* b2 = (const float*)d_in[8];
    const float* W3 = (const float*)d_in[9];
    const float* b3 = (const float*)d_in[10];
    const float* g1 = (const float*)d_in[11];
    const float* bt1 = (const float*)d_in[12];
    const float* g2 = (const float*)d_in[13];
    const float* bt2 = (const float*)d_in[14];
    const float* g3 = (const float*)d_in[15];
    const float* bt3 = (const float*)d_in[16];
    float* out = (float*)d_out;

    float *pA, *pB, *pStats;
    cudaGetSymbolAddress((void**)&pA, g_bufA);
    cudaGetSymbolAddress((void**)&pB, g_bufB);
    cudaGetSymbolAddress((void**)&pStats, g_stats);

    const int rowBlocks = (N_NODES + 127) / 128;  // 782
    const int L = NREP * 128;                      // stats stride per layer

    // launch order: k_layer1 is launch #4 (the one ncu -s 5 -c 1 captures)
    k_zero1<<<6250, 256>>>();
    k_zero2<<<1, 256>>>((const int*)ei);
    k_scatter<<<(N_EDGES * 16) / 256, 256>>>(ei, ea);
    k_layer1<<<rowBlocks, 256>>>(x, ga, batch, W1, b1, pA, pStats);
    k_layer64<<<rowBlocks, 256>>>(pA, W2, b2, pStats, g1, bt1, pB, pStats + L);
    k_layer64<<<rowBlocks, 256>>>(pB, W3, b3, pStats + L, g2, bt2, pA, pStats + 2 * L);
    k_final<<<(N_NODES * 16 + 255) / 256, 256>>>(pA, pStats + 2 * L, g3, bt3, out);
}